// round 7
// baseline (speedup 1.0000x reference)
#include <cuda_runtime.h>

#define NB 16
#define G 55                      // blocks per batch (55*16 = 880 <= 148*6)
#define NBLK (G * NB)             // 880
#define HWPIX (768*768)
#define NUM_IDS 128
#define NVEC (HWPIX/4)            // 147456
#define FXS 2048.0f
#define FXI (1.0f/2048.0f)
#define M26 ((1ull << 26) - 1)

typedef unsigned long long ull;

// ---- scratch (allocation-free __device__ globals). Partials are plain
// stores fully overwritten each run; ticket self-resets. ----
__device__ int   g_pcnt[NBLK * NUM_IDS];
__device__ float g_psin[NBLK * NUM_IDS];
__device__ float g_pcos[NBLK * NUM_IDS];
__device__ int   g_cnt [NB * NUM_IDS];
__device__ float g_fsin[NB * NUM_IDS];
__device__ float g_fcos[NB * NUM_IDS];
__device__ int   g_ni  [NB];
__device__ int   g_nbg [NB];
__device__ int   g_tix;

// ---------------------------------------------------------------------------
// K1: single fused streaming pass. Reads every input byte exactly once.
// Per pixel: ONE u64 atomicAdd into a per-WARP shared table:
//   bits [0,26)  = sum of round(|psin-gsin| * 2048)
//   bits [26,52) = sum of round(|pcos-gcos| * 2048)
//   bits [52,64) = pixel count
// Per-warp privatization (8 x 128 u64 = 8KB) kills cross-warp serialization.
// Flush = unpack + plain per-block partial stores. No tail.
// ---------------------------------------------------------------------------
__global__ void __launch_bounds__(256, 6)
k_main(const float* __restrict__ pred,
       const int*   __restrict__ inst,
       const float* __restrict__ gt) {
    const int tid  = threadIdx.x;
    const int warp = tid >> 5;
    const int b    = blockIdx.y;
    const int bx   = blockIdx.x;

    __shared__ ull sh[8][NUM_IDS];
    #pragma unroll
    for (int w = 0; w < 4; w++) sh[warp][(tid & 31) + 32 * w] = 0ULL;
    __syncthreads();

    ull* mt = sh[warp];
    const int4*   pi = (const int4*)(inst + (size_t)b * HWPIX);
    const float4* ps = (const float4*)(pred + (size_t)b * 2 * HWPIX);
    const float4* pc = (const float4*)(pred + (size_t)b * 2 * HWPIX + HWPIX);
    const float4* gs = (const float4*)(gt + (size_t)b * 5 * HWPIX + 2 * (size_t)HWPIX);
    const float4* gc = (const float4*)(gt + (size_t)b * 5 * HWPIX + 3 * (size_t)HWPIX);

    for (int i = bx * 256 + tid; i < NVEC; i += G * 256) {
        int4   id = __ldcs(pi + i);
        float4 s  = __ldcs(ps + i);
        float4 c  = __ldcs(pc + i);
        float4 g1 = __ldcs(gs + i);
        float4 g2 = __ldcs(gc + i);

        ull v0 = (ull)__float2uint_rn(fabsf(s.x - g1.x) * FXS)
               | ((ull)__float2uint_rn(fabsf(c.x - g2.x) * FXS) << 26)
               | (1ull << 52);
        ull v1 = (ull)__float2uint_rn(fabsf(s.y - g1.y) * FXS)
               | ((ull)__float2uint_rn(fabsf(c.y - g2.y) * FXS) << 26)
               | (1ull << 52);
        ull v2 = (ull)__float2uint_rn(fabsf(s.z - g1.z) * FXS)
               | ((ull)__float2uint_rn(fabsf(c.z - g2.z) * FXS) << 26)
               | (1ull << 52);
        ull v3 = (ull)__float2uint_rn(fabsf(s.w - g1.w) * FXS)
               | ((ull)__float2uint_rn(fabsf(c.w - g2.w) * FXS) << 26)
               | (1ull << 52);
        atomicAdd(&mt[id.x], v0);
        atomicAdd(&mt[id.y], v1);
        atomicAdd(&mt[id.z], v2);
        atomicAdd(&mt[id.w], v3);
    }
    __syncthreads();

    if (tid < NUM_IDS) {
        unsigned sn = 0, cs = 0, cn = 0;
        #pragma unroll
        for (int w = 0; w < 8; w++) {
            ull v = sh[w][tid];
            sn += (unsigned)(v & M26);
            cs += (unsigned)((v >> 26) & M26);
            cn += (unsigned)(v >> 52);
        }
        const int idx = (b * G + bx) * NUM_IDS + tid;
        g_pcnt[idx] = (int)cn;
        g_psin[idx] = (float)sn * FXI;
        g_pcos[idx] = (float)cs * FXI;
    }
}

// ---------------------------------------------------------------------------
// K2: finalize. 16 blocks x 128 threads; block b reduces batch b's partials.
// Ticket: last block computes global scalars and writes the 80 outputs.
// ---------------------------------------------------------------------------
__global__ void __launch_bounds__(128) k_fin(float* __restrict__ out) {
    const int b  = blockIdx.x;
    const int id = threadIdx.x;

    int   cn = 0;
    float fs = 0.0f, fc = 0.0f;
    #pragma unroll
    for (int x = 0; x < G; x++) {
        const int idx = (b * G + x) * NUM_IDS + id;
        cn += g_pcnt[idx];
        fs += g_psin[idx];
        fc += g_pcos[idx];
    }
    g_cnt [b * NUM_IDS + id] = cn;
    g_fsin[b * NUM_IDS + id] = fs;
    g_fcos[b * NUM_IDS + id] = fc;

    int myni = (id > 0 && cn > 0) ? 1 : 0;
    __shared__ int s_red[128];
    __shared__ int s_bg;
    if (id == 0) s_bg = cn;
    s_red[id] = myni;
    __syncthreads();
    for (int s = 64; s > 0; s >>= 1) {
        if (id < s) s_red[id] += s_red[id + s];
        __syncthreads();
    }
    if (id == 0) { g_ni[b] = s_red[0]; g_nbg[b] = s_bg; }

    // ticket: last block writes the output tuple
    __shared__ int s_last;
    if (id == 0) {
        __threadfence();
        s_last = (atomicAdd(&g_tix, 1) == NB - 1);
    }
    __syncthreads();
    if (!s_last) return;
    __threadfence();

    int ni = 0, nbg = 0;
    #pragma unroll
    for (int i = 0; i < NB; i++) { ni += g_ni[i]; nbg += g_nbg[i]; }
    const float inv_bg = 1.0f / (2.0f * (float)nbg);
    const float two_ni = 2.0f * (float)ni;

    const int warp = id >> 5, lane = id & 31;     // 4 warps
    for (int bb = warp; bb < NB; bb += 4) {
        float asin_ = 0.0f, acos_ = 0.0f;
        #pragma unroll
        for (int l = lane; l < NUM_IDS; l += 32) {
            const int idx = bb * NUM_IDS + l;
            int   c   = g_cnt[idx];
            float inv = (l == 0) ? inv_bg
                                 : ((c > 0) ? 1.0f / ((float)c * two_ni) : 0.0f);
            asin_ += g_fsin[idx] * inv;
            acos_ += g_fcos[idx] * inv;
        }
        for (int off = 16; off > 0; off >>= 1) {
            asin_ += __shfl_down_sync(0xFFFFFFFFu, asin_, off);
            acos_ += __shfl_down_sync(0xFFFFFFFFu, acos_, off);
        }
        if (lane == 0) {
            float t = asin_ + acos_;
            out[0 * NB + bb] = t;       // loss
            out[1 * NB + bb] = t;       // loss_direction_total
            out[2 * NB + bb] = 0.0f;    // loss_centers
            out[3 * NB + bb] = asin_;   // loss_sin
            out[4 * NB + bb] = acos_;   // loss_cos
        }
    }
    if (id == 0) g_tix = 0;             // self-reset for next graph replay
}

extern "C" void kernel_launch(void* const* d_in, const int* in_sizes, int n_in,
                              void* d_out, int out_size) {
    const float* pred = (const float*)d_in[0];   // (16,2,768,768) f32
    const int*   inst = (const int*)d_in[1];     // (16,768,768) i32
    // d_in[2] = labels (unused: W_FG == W_BG == 1)
    const float* gt   = (const float*)d_in[3];   // (16,5,768,768) f32
    float* out = (float*)d_out;                  // 80 f32

    k_main<<<dim3(G, NB), 256>>>(pred, inst, gt);
    k_fin<<<NB, 128>>>(out);
}

// round 9
// speedup vs baseline: 1.8344x; 1.8344x over previous
#include <cuda_runtime.h>

#define NB 16
#define GH 74                     // hist blocks per batch (74*16 = 1184 = 148*8)
#define G 37                      // loss blocks per batch (37*16 = 592 = 148*4)
#define NBLK (G * NB)
#define HWPIX (768*768)
#define NUM_IDS 128
#define NVEC (HWPIX/4)            // 147456

// ---- scratch (allocation-free __device__ globals). Plain stores fully
// overwritten each run; ticket self-resets. ----
__device__ unsigned char g_pack[(size_t)NB * HWPIX];  // ids packed to bytes
__device__ int   g_part [GH * NB * NUM_IDS];          // per-block partial hists
__device__ int   g_cnt  [NB * NUM_IDS];               // per-batch counts
__device__ int   g_ni   [NB];                         // per-batch #instances
__device__ int   g_nbg  [NB];                         // per-batch bg pixels
__device__ float g_ploss[NBLK * 2];                   // per-block (sin,cos)
__device__ int   g_tix;                               // loss ticket (self-reset)

// ---------------------------------------------------------------------------
// K1: histogram partials + id byte-packing.
// Per-WARP privatized shared tables (8 x 128, 32-bit) kill cross-warp
// same-address serialization. 8 blocks/SM for latency hiding.
// ---------------------------------------------------------------------------
__global__ void __launch_bounds__(256, 8) k_hist(const int* __restrict__ inst) {
    const int tid  = threadIdx.x;
    const int warp = tid >> 5;
    const int b    = blockIdx.y;
    const int bx   = blockIdx.x;

    __shared__ int sh[8][NUM_IDS];
    #pragma unroll
    for (int w = 0; w < 4; w++) sh[warp][(tid & 31) + 32 * w] = 0;
    __syncthreads();

    int* mt = sh[warp];
    const int4* pi = (const int4*)(inst + (size_t)b * HWPIX);
    uchar4*     pk = (uchar4*)(g_pack + (size_t)b * HWPIX);
    for (int i = bx * 256 + tid; i < NVEC; i += GH * 256) {
        int4 v = __ldcs(pi + i);
        pk[i] = make_uchar4((unsigned char)v.x, (unsigned char)v.y,
                            (unsigned char)v.z, (unsigned char)v.w);
        atomicAdd(&mt[v.x], 1);
        atomicAdd(&mt[v.y], 1);
        atomicAdd(&mt[v.z], 1);
        atomicAdd(&mt[v.w], 1);
    }
    __syncthreads();

    if (tid < NUM_IDS) {
        int tot = 0;
        #pragma unroll
        for (int w = 0; w < 8; w++) tot += sh[w][tid];
        g_part[(b * GH + bx) * NUM_IDS + tid] = tot;
    }
}

// ---------------------------------------------------------------------------
// K2: reduce partials. 16 blocks x 512 threads.
// Thread (id = tid&127, j = tid>>7) sums partials x = j, j+4, ... (coalesced
// across id, 4-way parallel over j) -> shared combine -> g_cnt, ni, nbg.
// ---------------------------------------------------------------------------
__global__ void __launch_bounds__(512) k_norm() {
    const int b   = blockIdx.x;
    const int tid = threadIdx.x;
    const int id  = tid & 127;
    const int j   = tid >> 7;          // 0..3

    int tot = 0;
    #pragma unroll
    for (int x = j; x < GH; x += 4)
        tot += g_part[(b * GH + x) * NUM_IDS + id];

    __shared__ int sp[4][NUM_IDS];
    sp[j][id] = tot;
    __syncthreads();

    __shared__ int s_red[NUM_IDS];
    __shared__ int s_bg;
    if (j == 0) {
        tot = sp[0][id] + sp[1][id] + sp[2][id] + sp[3][id];
        g_cnt[b * NUM_IDS + id] = tot;
        if (id == 0) s_bg = tot;
        s_red[id] = (id > 0 && tot > 0) ? 1 : 0;
    }
    __syncthreads();
    for (int s = 64; s > 0; s >>= 1) {
        if (j == 0 && id < s) s_red[id] += s_red[id + s];
        __syncthreads();
    }
    if (tid == 0) { g_ni[b] = s_red[0]; g_nbg[b] = s_bg; }
}

// ---------------------------------------------------------------------------
// K3: weighted-L1 stream (byte ids, streaming loads). One balanced wave.
// ---------------------------------------------------------------------------
__global__ void __launch_bounds__(256, 4) k_loss(const float* __restrict__ pred,
                                                 const float* __restrict__ gt,
                                                 float*       __restrict__ out) {
    const int tid = threadIdx.x;
    const int b   = blockIdx.y;
    const int bx  = blockIdx.x;
    const int bid = b * G + bx;

    __shared__ float s_inv[NUM_IDS];
    {
        int ni = 0, nbg = 0;
        #pragma unroll
        for (int i = 0; i < NB; i++) { ni += g_ni[i]; nbg += g_nbg[i]; }
        float inv_bg = 1.0f / (2.0f * (float)nbg);
        float two_ni = 2.0f * (float)ni;
        if (tid < NUM_IDS) {
            float c = (float)max(g_cnt[b * NUM_IDS + tid], 1);
            s_inv[tid] = (tid == 0) ? inv_bg : 1.0f / (c * two_ni);
        }
    }
    __syncthreads();

    const float4*   ps  = (const float4*)(pred + (size_t)b * 2 * HWPIX);
    const float4*   pc  = (const float4*)(pred + (size_t)b * 2 * HWPIX + HWPIX);
    const float4*   gs  = (const float4*)(gt + (size_t)b * 5 * HWPIX + 2 * (size_t)HWPIX);
    const float4*   gc  = (const float4*)(gt + (size_t)b * 5 * HWPIX + 3 * (size_t)HWPIX);
    const unsigned* pid = (const unsigned*)(g_pack + (size_t)b * HWPIX);

    float asin_ = 0.0f, acos_ = 0.0f;
    #pragma unroll 2
    for (int i = bx * 256 + tid; i < NVEC; i += G * 256) {
        unsigned w  = __ldcs(pid + i);
        float4   s  = __ldcs(ps + i);
        float4   c  = __ldcs(pc + i);
        float4   g1 = __ldcs(gs + i);
        float4   g2 = __ldcs(gc + i);
        float w0 = s_inv[w & 0xFF];
        float w1 = s_inv[(w >> 8)  & 0xFF];
        float w2 = s_inv[(w >> 16) & 0xFF];
        float w3 = s_inv[w >> 24];
        asin_ += w0 * fabsf(s.x - g1.x) + w1 * fabsf(s.y - g1.y)
               + w2 * fabsf(s.z - g1.z) + w3 * fabsf(s.w - g1.w);
        acos_ += w0 * fabsf(c.x - g2.x) + w1 * fabsf(c.y - g2.y)
               + w2 * fabsf(c.z - g2.z) + w3 * fabsf(c.w - g2.w);
    }

    // block reduce
    for (int off = 16; off > 0; off >>= 1) {
        asin_ += __shfl_down_sync(0xFFFFFFFFu, asin_, off);
        acos_ += __shfl_down_sync(0xFFFFFFFFu, acos_, off);
    }
    __shared__ float ws[8], wc[8];
    const int lane = tid & 31, warp = tid >> 5;
    if (lane == 0) { ws[warp] = asin_; wc[warp] = acos_; }
    __syncthreads();
    if (tid == 0) {
        float vs = 0.0f, vc = 0.0f;
        #pragma unroll
        for (int i = 0; i < 8; i++) { vs += ws[i]; vc += wc[i]; }
        g_ploss[bid * 2 + 0] = vs;
        g_ploss[bid * 2 + 1] = vc;
    }

    // global ticket: last block writes the 5x16 output tuple
    __shared__ int s_last;
    if (tid == 0) {
        __threadfence();
        s_last = (atomicAdd(&g_tix, 1) == NBLK - 1);
    }
    __syncthreads();
    if (!s_last) return;
    __threadfence();

    for (int bb = warp; bb < NB; bb += 8) {      // warp w -> batches w, w+8
        float ss = 0.0f, cc = 0.0f;
        for (int x = lane; x < G; x += 32) {
            ss += g_ploss[(bb * G + x) * 2 + 0];
            cc += g_ploss[(bb * G + x) * 2 + 1];
        }
        for (int off = 16; off > 0; off >>= 1) {
            ss += __shfl_down_sync(0xFFFFFFFFu, ss, off);
            cc += __shfl_down_sync(0xFFFFFFFFu, cc, off);
        }
        if (lane == 0) {
            float t = ss + cc;
            out[0 * NB + bb] = t;      // loss
            out[1 * NB + bb] = t;      // loss_direction_total
            out[2 * NB + bb] = 0.0f;   // loss_centers
            out[3 * NB + bb] = ss;     // loss_sin
            out[4 * NB + bb] = cc;     // loss_cos
        }
    }
    if (tid == 0) g_tix = 0;           // self-reset for next graph replay
}

extern "C" void kernel_launch(void* const* d_in, const int* in_sizes, int n_in,
                              void* d_out, int out_size) {
    const float* pred = (const float*)d_in[0];   // (16,2,768,768) f32
    const int*   inst = (const int*)d_in[1];     // (16,768,768) i32
    // d_in[2] = labels (unused: W_FG == W_BG == 1)
    const float* gt   = (const float*)d_in[3];   // (16,5,768,768) f32
    float* out = (float*)d_out;                  // 80 f32

    k_hist<<<dim3(GH, NB), 256>>>(inst);
    k_norm<<<NB, 512>>>();
    k_loss<<<dim3(G, NB), 256>>>(pred, gt, out);
}

// round 10
// speedup vs baseline: 1.8358x; 1.0008x over previous
#include <cuda_runtime.h>

#define NB 16
#define GH 74                     // hist blocks per batch (74*16 = 1184 = 148*8)
#define G 37                      // loss blocks per batch (37*16 = 592 = 148*4)
#define NBLK (G * NB)
#define HWPIX (768*768)
#define NUM_IDS 128
#define NVEC (HWPIX/4)            // 147456

// ---- scratch (allocation-free __device__ globals). Plain stores fully
// overwritten each run; tickets self-reset. ----
__device__ unsigned char g_pack[(size_t)NB * HWPIX];  // ids packed to bytes
__device__ int   g_part [GH * NB * NUM_IDS];          // per-block partial hists
__device__ int   g_cnt  [NB * NUM_IDS];               // per-batch counts
__device__ int   g_ni   [NB];                         // per-batch #instances
__device__ int   g_nbg  [NB];                         // per-batch bg pixels
__device__ float g_ploss[NBLK * 2];                   // per-block (sin,cos)
__device__ int   g_tixh [NB];                         // per-batch hist tickets
__device__ int   g_tix;                               // loss ticket

// ---------------------------------------------------------------------------
// K1: histogram partials + id byte-packing, with a PARALLEL per-batch ticket
// tail that produces g_cnt / g_ni / g_nbg (replaces the k_norm launch).
// Per-WARP privatized shared tables kill cross-warp atomic serialization.
// ---------------------------------------------------------------------------
__global__ void __launch_bounds__(256, 8) k_hist(const int* __restrict__ inst) {
    const int tid  = threadIdx.x;
    const int warp = tid >> 5;
    const int lane = tid & 31;
    const int b    = blockIdx.y;
    const int bx   = blockIdx.x;

    __shared__ int sh[8][NUM_IDS];
    #pragma unroll
    for (int w = 0; w < 4; w++) sh[warp][lane + 32 * w] = 0;
    __syncthreads();

    int* mt = sh[warp];
    const int4* pi = (const int4*)(inst + (size_t)b * HWPIX);
    uchar4*     pk = (uchar4*)(g_pack + (size_t)b * HWPIX);
    for (int i = bx * 256 + tid; i < NVEC; i += GH * 256) {
        int4 v = __ldcs(pi + i);
        pk[i] = make_uchar4((unsigned char)v.x, (unsigned char)v.y,
                            (unsigned char)v.z, (unsigned char)v.w);
        atomicAdd(&mt[v.x], 1);
        atomicAdd(&mt[v.y], 1);
        atomicAdd(&mt[v.z], 1);
        atomicAdd(&mt[v.w], 1);
    }
    __syncthreads();

    if (tid < NUM_IDS) {
        int tot = 0;
        #pragma unroll
        for (int w = 0; w < 8; w++) tot += sh[w][tid];
        g_part[(b * GH + bx) * NUM_IDS + tid] = tot;
    }

    // ---- per-batch ticket: last block of this batch reduces the partials ---
    __shared__ int s_last;
    if (tid == 0) {
        __threadfence();
        s_last = (atomicAdd(&g_tixh[b], 1) == GH - 1);
    }
    __syncthreads();
    if (!s_last) return;
    __threadfence();

    // parallel reduce: id = tid&127, j = tid>>7 handles every 2nd partial
    const int id = tid & 127;
    const int j  = tid >> 7;           // 0..1
    int tot = 0;
    #pragma unroll
    for (int x = j; x < GH; x += 2)
        tot += g_part[(b * GH + x) * NUM_IDS + id];

    __shared__ int sp[2][NUM_IDS];
    sp[j][id] = tot;
    __syncthreads();

    __shared__ int s_wni[4];
    if (j == 0) {                      // tid 0..127 = warps 0..3, full warps
        tot += sp[1][id];
        g_cnt[b * NUM_IDS + id] = tot;
        unsigned ball = __ballot_sync(0xFFFFFFFFu, id > 0 && tot > 0);
        if (lane == 0) s_wni[warp] = __popc(ball);
        if (id == 0) g_nbg[b] = tot;
    }
    __syncthreads();
    if (tid == 0) {
        g_ni[b]   = s_wni[0] + s_wni[1] + s_wni[2] + s_wni[3];
        g_tixh[b] = 0;                 // self-reset for next graph replay
    }
}

// ---------------------------------------------------------------------------
// K2: weighted-L1 stream (byte ids, streaming loads). One balanced wave.
// ---------------------------------------------------------------------------
__global__ void __launch_bounds__(256, 4) k_loss(const float* __restrict__ pred,
                                                 const float* __restrict__ gt,
                                                 float*       __restrict__ out) {
    const int tid = threadIdx.x;
    const int b   = blockIdx.y;
    const int bx  = blockIdx.x;
    const int bid = b * G + bx;

    __shared__ float s_inv[NUM_IDS];
    {
        int ni = 0, nbg = 0;
        #pragma unroll
        for (int i = 0; i < NB; i++) { ni += g_ni[i]; nbg += g_nbg[i]; }
        float inv_bg = 1.0f / (2.0f * (float)nbg);
        float two_ni = 2.0f * (float)ni;
        if (tid < NUM_IDS) {
            float c = (float)max(g_cnt[b * NUM_IDS + tid], 1);
            s_inv[tid] = (tid == 0) ? inv_bg : 1.0f / (c * two_ni);
        }
    }
    __syncthreads();

    const float4*   ps  = (const float4*)(pred + (size_t)b * 2 * HWPIX);
    const float4*   pc  = (const float4*)(pred + (size_t)b * 2 * HWPIX + HWPIX);
    const float4*   gs  = (const float4*)(gt + (size_t)b * 5 * HWPIX + 2 * (size_t)HWPIX);
    const float4*   gc  = (const float4*)(gt + (size_t)b * 5 * HWPIX + 3 * (size_t)HWPIX);
    const unsigned* pid = (const unsigned*)(g_pack + (size_t)b * HWPIX);

    float asin_ = 0.0f, acos_ = 0.0f;
    #pragma unroll 2
    for (int i = bx * 256 + tid; i < NVEC; i += G * 256) {
        unsigned w  = __ldcs(pid + i);
        float4   s  = __ldcs(ps + i);
        float4   c  = __ldcs(pc + i);
        float4   g1 = __ldcs(gs + i);
        float4   g2 = __ldcs(gc + i);
        float w0 = s_inv[w & 0xFF];
        float w1 = s_inv[(w >> 8)  & 0xFF];
        float w2 = s_inv[(w >> 16) & 0xFF];
        float w3 = s_inv[w >> 24];
        asin_ += w0 * fabsf(s.x - g1.x) + w1 * fabsf(s.y - g1.y)
               + w2 * fabsf(s.z - g1.z) + w3 * fabsf(s.w - g1.w);
        acos_ += w0 * fabsf(c.x - g2.x) + w1 * fabsf(c.y - g2.y)
               + w2 * fabsf(c.z - g2.z) + w3 * fabsf(c.w - g2.w);
    }

    // block reduce
    for (int off = 16; off > 0; off >>= 1) {
        asin_ += __shfl_down_sync(0xFFFFFFFFu, asin_, off);
        acos_ += __shfl_down_sync(0xFFFFFFFFu, acos_, off);
    }
    __shared__ float ws[8], wc[8];
    const int lane = tid & 31, warp = tid >> 5;
    if (lane == 0) { ws[warp] = asin_; wc[warp] = acos_; }
    __syncthreads();
    if (tid == 0) {
        float vs = 0.0f, vc = 0.0f;
        #pragma unroll
        for (int i = 0; i < 8; i++) { vs += ws[i]; vc += wc[i]; }
        g_ploss[bid * 2 + 0] = vs;
        g_ploss[bid * 2 + 1] = vc;
    }

    // global ticket: last block writes the 5x16 output tuple
    __shared__ int s_last;
    if (tid == 0) {
        __threadfence();
        s_last = (atomicAdd(&g_tix, 1) == NBLK - 1);
    }
    __syncthreads();
    if (!s_last) return;
    __threadfence();

    for (int bb = warp; bb < NB; bb += 8) {      // warp w -> batches w, w+8
        float ss = 0.0f, cc = 0.0f;
        for (int x = lane; x < G; x += 32) {
            ss += g_ploss[(bb * G + x) * 2 + 0];
            cc += g_ploss[(bb * G + x) * 2 + 1];
        }
        for (int off = 16; off > 0; off >>= 1) {
            ss += __shfl_down_sync(0xFFFFFFFFu, ss, off);
            cc += __shfl_down_sync(0xFFFFFFFFu, cc, off);
        }
        if (lane == 0) {
            float t = ss + cc;
            out[0 * NB + bb] = t;      // loss
            out[1 * NB + bb] = t;      // loss_direction_total
            out[2 * NB + bb] = 0.0f;   // loss_centers
            out[3 * NB + bb] = ss;     // loss_sin
            out[4 * NB + bb] = cc;     // loss_cos
        }
    }
    if (tid == 0) g_tix = 0;           // self-reset for next graph replay
}

extern "C" void kernel_launch(void* const* d_in, const int* in_sizes, int n_in,
                              void* d_out, int out_size) {
    const float* pred = (const float*)d_in[0];   // (16,2,768,768) f32
    const int*   inst = (const int*)d_in[1];     // (16,768,768) i32
    // d_in[2] = labels (unused: W_FG == W_BG == 1)
    const float* gt   = (const float*)d_in[3];   // (16,5,768,768) f32
    float* out = (float*)d_out;                  // 80 f32

    k_hist<<<dim3(GH, NB), 256>>>(inst);
    k_loss<<<dim3(G, NB), 256>>>(pred, gt, out);
}